// round 9
// baseline (speedup 1.0000x reference)
#include <cuda_runtime.h>
#include <math.h>

#define TT 512
#define BB 128
#define DD 128
#define HH 256
#define CC 10
#define G4 1024
#define MROWS (TT*BB)
#define NCTA 128
#define HS_LD 264                 // h stage row stride (floats)

// ---------------- static device scratch (no runtime allocation) ----------------
__device__ float g_e  [(size_t)MROWS * DD];        //  32 MB embedded inputs [t*B+b, D]
__device__ float g_XwF[(size_t)MROWS * G4];        // 256 MB x@W fwd (reused layer 2)
__device__ float g_XwB[(size_t)MROWS * G4];        // 256 MB x@W bwd (reused layer 2)
__device__ float g_seq[(size_t)MROWS * 2 * HH];    // 128 MB layer-1 output sequence
__device__ float g_state[4 * BB * HH];             // final h per dir (final_k input)

// packed dual-fp32 FMA
__device__ __forceinline__ void ffma2(float2 &d, float2 a, float2 b) {
    asm("fma.rn.f32x2 %0, %1, %2, %0;"
        : "+l"(*reinterpret_cast<unsigned long long*>(&d))
        : "l"(*reinterpret_cast<unsigned long long*>(&a)),
          "l"(*reinterpret_cast<unsigned long long*>(&b)));
}

__device__ __forceinline__ float sigf(float x) {
    return __fdividef(1.0f, 1.0f + __expf(-x));
}
__device__ __forceinline__ float tanhfast(float x) {
    return __fdividef(2.0f, 1.0f + __expf(-2.0f * x)) - 1.0f;
}

// cluster DSMEM helpers
__device__ __forceinline__ unsigned mapa_rank(unsigned addr, unsigned rank) {
    unsigned r;
    asm("mapa.shared::cluster.u32 %0, %1, %2;" : "=r"(r) : "r"(addr), "r"(rank));
    return r;
}
__device__ __forceinline__ void st_dsmem64(unsigned addr, float x, float y) {
    float2 v = make_float2(x, y);
    asm volatile("st.shared::cluster.b64 [%0], %1;"
                 :: "r"(addr), "l"(*reinterpret_cast<unsigned long long*>(&v))
                 : "memory");
}
__device__ __forceinline__ unsigned smem_u32(const void* p) {
    return (unsigned)__cvta_generic_to_shared(p);
}

// cp.async 16B (GEMM path)
__device__ __forceinline__ void cpa16(unsigned dst, const void* src) {
    asm volatile("cp.async.cg.shared.global [%0], [%1], 16;" :: "r"(dst), "l"(src));
}
#define CPA_COMMIT() asm volatile("cp.async.commit_group;")
#define CPA_WAIT0()  asm volatile("cp.async.wait_group 0;")

__device__ __forceinline__ unsigned f2tf32(float x) {
    unsigned r; asm("cvt.rna.tf32.f32 %0, %1;" : "=r"(r) : "f"(x)); return r;
}
__device__ __forceinline__ void mma_tf32(float* c, const unsigned* a, const unsigned* b) {
    asm("mma.sync.aligned.m16n8k8.row.col.f32.tf32.tf32.f32 "
        "{%0,%1,%2,%3}, {%4,%5,%6,%7}, {%8,%9}, {%0,%1,%2,%3};"
        : "+f"(c[0]), "+f"(c[1]), "+f"(c[2]), "+f"(c[3])
        : "r"(a[0]), "r"(a[1]), "r"(a[2]), "r"(a[3]), "r"(b[0]), "r"(b[1]));
}

// ---------------- embedding gather ----------------
__global__ void embed_k(const int* __restrict__ x, const float* __restrict__ emb) {
    int gid = blockIdx.x * blockDim.x + threadIdx.x;
    int r  = gid >> 5;
    int c4 = gid & 31;
    int t  = r >> 7;
    int b  = r & 127;
    int tok = x[b * TT + t];
    reinterpret_cast<float4*>(g_e)[(size_t)r * 32 + c4] =
        reinterpret_cast<const float4*>(emb)[(size_t)tok * 32 + c4];
}

// ---------------- 3xTF32 tensor-core GEMM + bias (unchanged from R7) ----------------
#define AS_LD 20
#define BS_LD 136
__global__ __launch_bounds__(256) void gemm_k(int a_sel, int c_sel,
        const float* __restrict__ W, const float* __restrict__ bias, int K)
{
    const float* A = a_sel ? g_seq : g_e;
    float*       C = c_sel ? g_XwB : g_XwF;

    __shared__ __align__(16) float As[2][128][AS_LD];
    __shared__ __align__(16) float Bs[2][16][BS_LD];

    const int m0   = blockIdx.x * 128;
    const int n0   = blockIdx.y * 128;
    const int tid  = threadIdx.x;
    const int lane = tid & 31;
    const int warp = tid >> 5;
    const int gid  = lane >> 2;
    const int tig  = lane & 3;
    const int wm   = warp & 3;
    const int wn   = warp >> 2;

    const unsigned sA = smem_u32(&As[0][0][0]);
    const unsigned sB = smem_u32(&Bs[0][0][0]);
    const unsigned bufA = 128 * AS_LD * 4;
    const unsigned bufB = 16 * BS_LD * 4;

    float acc[2][8][4];
#pragma unroll
    for (int mb = 0; mb < 2; ++mb)
#pragma unroll
        for (int nb = 0; nb < 8; ++nb)
#pragma unroll
            for (int r = 0; r < 4; ++r) acc[mb][nb][r] = 0.f;

    const int nk = K >> 4;

    auto load_tile = [&](int buf, int kt) {
#pragma unroll
        for (int i = 0; i < 2; ++i) {
            int id = tid + i * 256;
            int r = id >> 2, kq = id & 3;
            cpa16(sA + buf * bufA + (unsigned)((r * AS_LD + kq * 4) * 4),
                  A + (size_t)(m0 + r) * K + kt + kq * 4);
        }
#pragma unroll
        for (int i = 0; i < 2; ++i) {
            int id = tid + i * 256;
            int r = id >> 5, c4 = (id & 31) * 4;
            cpa16(sB + buf * bufB + (unsigned)((r * BS_LD + c4) * 4),
                  W + (size_t)(kt + r) * G4 + n0 + c4);
        }
        CPA_COMMIT();
    };

    load_tile(0, 0);
    CPA_WAIT0();
    __syncthreads();

    for (int kt = 0; kt < nk; ++kt) {
        const int cur = kt & 1;
        const bool more = (kt + 1) < nk;
        if (more) load_tile(cur ^ 1, (kt + 1) << 4);

#pragma unroll
        for (int kh = 0; kh < 2; ++kh) {
            const int k0 = kh * 8;
            unsigned ahi[2][4], alo[2][4];
#pragma unroll
            for (int mb = 0; mb < 2; ++mb) {
                const int rbase = wm * 32 + mb * 16 + gid;
#pragma unroll
                for (int r = 0; r < 4; ++r) {
                    float v = As[cur][rbase + (r & 1) * 8][k0 + tig + (r >> 1) * 4];
                    unsigned h = f2tf32(v);
                    ahi[mb][r] = h;
                    alo[mb][r] = f2tf32(v - __uint_as_float(h));
                }
            }
#pragma unroll
            for (int nb = 0; nb < 8; ++nb) {
                const int nc = wn * 64 + nb * 8 + gid;
                float b0 = Bs[cur][k0 + tig][nc];
                float b1 = Bs[cur][k0 + tig + 4][nc];
                unsigned bh[2], bl[2];
                bh[0] = f2tf32(b0); bl[0] = f2tf32(b0 - __uint_as_float(bh[0]));
                bh[1] = f2tf32(b1); bl[1] = f2tf32(b1 - __uint_as_float(bh[1]));
#pragma unroll
                for (int mb = 0; mb < 2; ++mb) mma_tf32(acc[mb][nb], ahi[mb], bh);
#pragma unroll
                for (int mb = 0; mb < 2; ++mb) mma_tf32(acc[mb][nb], ahi[mb], bl);
#pragma unroll
                for (int mb = 0; mb < 2; ++mb) mma_tf32(acc[mb][nb], alo[mb], bh);
            }
        }
        if (more) {
            CPA_WAIT0();
            __syncthreads();
        }
    }

#pragma unroll
    for (int mb = 0; mb < 2; ++mb) {
        const int row0 = m0 + wm * 32 + mb * 16 + gid;
#pragma unroll
        for (int nb = 0; nb < 8; ++nb) {
            const int col = n0 + wn * 64 + nb * 8 + tig * 2;
            float2 bv = *reinterpret_cast<const float2*>(bias + col);
            float2 v0 = make_float2(acc[mb][nb][0] + bv.x, acc[mb][nb][1] + bv.y);
            float2 v1 = make_float2(acc[mb][nb][2] + bv.x, acc[mb][nb][3] + bv.y);
            *reinterpret_cast<float2*>(C + (size_t)row0 * G4 + col)       = v0;
            *reinterpret_cast<float2*>(C + (size_t)(row0 + 8) * G4 + col) = v1;
        }
    }
}

// ---------------- persistent bidirectional LSTM: 8-CTA cluster + DSMEM exchange ----
// bid = dir*64 + bt*8 + nt; cluster = the 8 nt-CTAs of one (dir, bt). Cluster rank
// == nt. Per step: k-loop reads h(s-1) from LOCAL smem hstage[s&1]; after gates,
// each thread writes its 4 h values into hstage[(s+1)&1] of ALL 8 cluster CTAs via
// mapa + st.shared::cluster; one barrier.cluster (release/acquire) ends the step.
// No L2 fences, flags, or global h buffers. Clusters are self-contained (no
// cross-cluster dependency), so co-residency is not required for progress.
// dyn smem: Us[256][128] + hstage[2][16][HS_LD]
__global__ __launch_bounds__(128) void __cluster_dims__(8, 1, 1)
lstm_persist_k(const float* __restrict__ Uf, const float* __restrict__ Ub,
               int write_seq)
{
    extern __shared__ float smp[];
    float* Us = smp;                                  // 256*128 floats
    float (*hstage)[16][HS_LD] =
        reinterpret_cast<float (*)[16][HS_LD]>(smp + 256 * 128);

    const int bid = blockIdx.x;
    const int dir = bid >> 6;
    const int bt  = (bid >> 3) & 7;
    const int nt  = bid & 7;
    const int tid = threadIdx.x;

    const float* U  = dir ? Ub : Uf;
    const float* Xw = dir ? g_XwB : g_XwF;

    // load U slice: Us[k*128 + g*32 + ln] = U[k*G4 + g*HH + nt*32 + ln]
    for (int i = tid; i < 256 * 32; i += 128) {
        int k = i >> 5;
        int col = (i & 31) * 4;
        int g = col >> 5, ln = col & 31;
        *reinterpret_cast<float4*>(&Us[k * 128 + col]) =
            *reinterpret_cast<const float4*>(U + (size_t)k * G4 + g * HH + nt * 32 + ln);
    }
    // zero h(-1) stage (parity 0), local only
    for (int i = tid; i < 16 * HS_LD * 2; i += 128) hstage[0][0][i & 0x7fffffff] = 0.f;
    __syncthreads();

    const int b_half = tid >> 4;
    const int n_grp  = tid & 15;
    const int nloc   = n_grp * 2;
    const int ngl    = nt * 32 + nloc;
    const int r0     = bt * 16 + b_half * 2;

    // my h slot (row r0, col ngl) inside hstage[p]
    const unsigned hs0 = smem_u32(&hstage[0][b_half * 2][ngl]);
    const unsigned hs1 = smem_u32(&hstage[1][b_half * 2][ngl]);

    float2 cst[2] = {make_float2(0.f, 0.f), make_float2(0.f, 0.f)};

    for (int s = 0; s < TT; ++s) {
        const int t   = dir ? (TT - 1 - s) : s;
        const int par = s & 1;

        // xW for my 2 rows x 2 cols x 4 gates (issued now, consumed after k-loop)
        const float* xw0 = Xw + ((size_t)t * BB + r0) * G4 + ngl;
        const float* xw1 = xw0 + G4;
        float2 x0[4], x1[4];
#pragma unroll
        for (int g = 0; g < 4; ++g) {
            x0[g] = *reinterpret_cast<const float2*>(xw0 + g * HH);
            x1[g] = *reinterpret_cast<const float2*>(xw1 + g * HH);
        }

        float2 acc[4][2];
#pragma unroll
        for (int g = 0; g < 4; ++g) {
            acc[g][0] = make_float2(0.f, 0.f);
            acc[g][1] = make_float2(0.f, 0.f);
        }

        const float* sr0 = hstage[par][b_half * 2];
        const float* sr1 = hstage[par][b_half * 2 + 1];
        const float* Up  = Us + nloc;

#pragma unroll 4
        for (int k4 = 0; k4 < HH; k4 += 4) {
            float4 h0v = *reinterpret_cast<const float4*>(sr0 + k4);
            float4 h1v = *reinterpret_cast<const float4*>(sr1 + k4);
            const float h0a[4] = {h0v.x, h0v.y, h0v.z, h0v.w};
            const float h1a[4] = {h1v.x, h1v.y, h1v.z, h1v.w};
#pragma unroll
            for (int kk = 0; kk < 4; ++kk) {
                const float* row = Up + (size_t)(k4 + kk) * 128;
                float2 hh0 = make_float2(h0a[kk], h0a[kk]);
                float2 hh1 = make_float2(h1a[kk], h1a[kk]);
#pragma unroll
                for (int g = 0; g < 4; ++g) {
                    float2 u2 = *reinterpret_cast<const float2*>(row + g * 32);
                    ffma2(acc[g][0], u2, hh0);
                    ffma2(acc[g][1], u2, hh1);
                }
            }
        }

        // gates + state update
        float2 hnew[2];
#pragma unroll
        for (int bb = 0; bb < 2; ++bb) {
            const float2* xg = bb ? x1 : x0;
            float zi0 = acc[0][bb].x + xg[0].x, zi1 = acc[0][bb].y + xg[0].y;
            float zf0 = acc[1][bb].x + xg[1].x, zf1 = acc[1][bb].y + xg[1].y;
            float zg0 = acc[2][bb].x + xg[2].x, zg1 = acc[2][bb].y + xg[2].y;
            float zo0 = acc[3][bb].x + xg[3].x, zo1 = acc[3][bb].y + xg[3].y;
            float c0 = sigf(zf0) * cst[bb].x + sigf(zi0) * tanhfast(zg0);
            float c1 = sigf(zf1) * cst[bb].y + sigf(zi1) * tanhfast(zg1);
            cst[bb] = make_float2(c0, c1);
            hnew[bb] = make_float2(sigf(zo0) * tanhfast(c0),
                                   sigf(zo1) * tanhfast(c1));
        }

        // broadcast h(s) into hstage[par^1] of all 8 cluster CTAs (incl. self)
        const unsigned dst = par ? hs0 : hs1;
#pragma unroll
        for (int rk = 0; rk < 8; ++rk) {
            unsigned ra = mapa_rank(dst, (unsigned)rk);
            st_dsmem64(ra,               hnew[0].x, hnew[0].y);
            st_dsmem64(ra + HS_LD * 4,   hnew[1].x, hnew[1].y);
        }

        if (write_seq) {
#pragma unroll
            for (int bb = 0; bb < 2; ++bb)
                *reinterpret_cast<float2*>(
                    g_seq + ((size_t)t * BB + r0 + bb) * (2 * HH) + dir * HH + ngl) =
                    hnew[bb];
        }
        if (s == TT - 1) {
#pragma unroll
            for (int bb = 0; bb < 2; ++bb)
                *reinterpret_cast<float2*>(
                    g_state + (size_t)dir * 2 * BB * HH + (size_t)(r0 + bb) * HH + ngl) =
                    hnew[bb];
        }

        // end of step: release my DSMEM stores, acquire peers'
        asm volatile("barrier.cluster.arrive.aligned;" ::: "memory");
        asm volatile("barrier.cluster.wait.aligned;"   ::: "memory");
    }
}

// ---------------- final dense + softmax ----------------
__global__ void final_k(const float* __restrict__ Wd, const float* __restrict__ bd,
                        float* __restrict__ out)
{
    int b = blockIdx.x, lane = threadIdx.x;
    const float* hf = g_state;
    const float* hb = g_state + 2 * BB * HH;
    float acc[CC];
#pragma unroll
    for (int c = 0; c < CC; ++c) acc[c] = 0.f;
    for (int k = lane; k < 2 * HH; k += 32) {
        float hv = (k < HH) ? hf[(size_t)b * HH + k] : hb[(size_t)b * HH + k - HH];
        const float* w = Wd + (size_t)k * CC;
#pragma unroll
        for (int c = 0; c < CC; ++c) acc[c] = fmaf(hv, w[c], acc[c]);
    }
#pragma unroll
    for (int c = 0; c < CC; ++c)
#pragma unroll
        for (int o = 16; o; o >>= 1) acc[c] += __shfl_down_sync(0xffffffffu, acc[c], o);
    if (lane == 0) {
        float m = -1e30f;
#pragma unroll
        for (int c = 0; c < CC; ++c) { acc[c] += bd[c]; m = fmaxf(m, acc[c]); }
        float e[CC], s = 0.f;
#pragma unroll
        for (int c = 0; c < CC; ++c) { e[c] = expf(acc[c] - m); s += e[c]; }
        float inv = 1.f / s;
#pragma unroll
        for (int c = 0; c < CC; ++c) out[b * CC + c] = e[c] * inv;
    }
}

extern "C" void kernel_launch(void* const* d_in, const int* in_sizes, int n_in,
                              void* d_out, int out_size)
{
    const int*   x   = (const int*)  d_in[0];
    const float* emb = (const float*)d_in[1];
    const float* W1f = (const float*)d_in[2];
    const float* U1f = (const float*)d_in[3];
    const float* b1f = (const float*)d_in[4];
    const float* W1b = (const float*)d_in[5];
    const float* U1b = (const float*)d_in[6];
    const float* b1b = (const float*)d_in[7];
    const float* W2f = (const float*)d_in[8];
    const float* U2f = (const float*)d_in[9];
    const float* b2f = (const float*)d_in[10];
    const float* W2b = (const float*)d_in[11];
    const float* U2b = (const float*)d_in[12];
    const float* b2b = (const float*)d_in[13];
    const float* Wd  = (const float*)d_in[14];
    const float* bd  = (const float*)d_in[15];
    float* out = (float*)d_out;

    const int LSTM_SMEM = 256 * 128 * 4 + 2 * 16 * HS_LD * 4;   // 131072 + 33792

    static int smem_set = 0;
    if (!smem_set) {
        cudaFuncSetAttribute(lstm_persist_k,
                             cudaFuncAttributeMaxDynamicSharedMemorySize, LSTM_SMEM);
        smem_set = 1;
    }

    embed_k<<<(MROWS * 32) / 256, 256>>>(x, emb);

    dim3 gg(MROWS / 128, G4 / 128);

    // layer 1
    gemm_k<<<gg, 256>>>(0, 0, W1f, b1f, DD);
    gemm_k<<<gg, 256>>>(0, 1, W1b, b1b, DD);
    lstm_persist_k<<<NCTA, 128, LSTM_SMEM>>>(U1f, U1b, 1);

    // layer 2
    gemm_k<<<gg, 256>>>(1, 0, W2f, b2f, 2 * HH);
    gemm_k<<<gg, 256>>>(1, 1, W2b, b2b, 2 * HH);
    lstm_persist_k<<<NCTA, 128, LSTM_SMEM>>>(U2f, U2b, 0);

    final_k<<<BB, 32>>>(Wd, bd, out);
}

// round 10
// speedup vs baseline: 1.1649x; 1.1649x over previous
#include <cuda_runtime.h>
#include <math.h>

#define TT 512
#define BB 128
#define DD 128
#define HH 256
#define CC 10
#define G4 1024
#define MROWS (TT*BB)
#define NCTA 128
#define NGRP 8            // CTAs per barrier group = one (dir, batch-tile)

// ---------------- static device scratch (no runtime allocation) ----------------
__device__ float g_e  [(size_t)MROWS * DD];        //  32 MB embedded inputs [t*B+b, D]
__device__ float g_XwF[(size_t)MROWS * G4];        // 256 MB x@W fwd (reused layer 2)
__device__ float g_XwB[(size_t)MROWS * G4];        // 256 MB x@W bwd (reused layer 2)
__device__ float g_seq[(size_t)MROWS * 2 * HH];    // 128 MB layer-1 output sequence
__device__ float g_state[4 * BB * HH];             // per dir: h parity buf0, buf1
__device__ unsigned g_bcount[16 * 32];             // per-group arrive counters (128B lines)
__device__ unsigned g_bepoch[16 * 32];             // per-group epochs (128B lines)

// packed dual-fp32 FMA
__device__ __forceinline__ void ffma2(float2 &d, float2 a, float2 b) {
    asm("fma.rn.f32x2 %0, %1, %2, %0;"
        : "+l"(*reinterpret_cast<unsigned long long*>(&d))
        : "l"(*reinterpret_cast<unsigned long long*>(&a)),
          "l"(*reinterpret_cast<unsigned long long*>(&b)));
}

__device__ __forceinline__ float sigf(float x) {
    return __fdividef(1.0f, 1.0f + __expf(-x));
}
__device__ __forceinline__ float tanhfast(float x) {
    return __fdividef(2.0f, 1.0f + __expf(-2.0f * x)) - 1.0f;
}

// cp.async 16B (GEMM path)
__device__ __forceinline__ void cpa16(unsigned dst, const void* src) {
    asm volatile("cp.async.cg.shared.global [%0], [%1], 16;" :: "r"(dst), "l"(src));
}
#define CPA_COMMIT() asm volatile("cp.async.commit_group;")
#define CPA_WAIT0()  asm volatile("cp.async.wait_group 0;")

__device__ __forceinline__ unsigned f2tf32(float x) {
    unsigned r; asm("cvt.rna.tf32.f32 %0, %1;" : "=r"(r) : "f"(x)); return r;
}
__device__ __forceinline__ void mma_tf32(float* c, const unsigned* a, const unsigned* b) {
    asm("mma.sync.aligned.m16n8k8.row.col.f32.tf32.tf32.f32 "
        "{%0,%1,%2,%3}, {%4,%5,%6,%7}, {%8,%9}, {%0,%1,%2,%3};"
        : "+f"(c[0]), "+f"(c[1]), "+f"(c[2]), "+f"(c[3])
        : "r"(a[0]), "r"(a[1]), "r"(a[2]), "r"(a[3]), "r"(b[0]), "r"(b[1]));
}

// per-group software barrier: 8 CTAs sharing one (dir, batch-tile)
__device__ __forceinline__ void grid_bar(int grp, unsigned &epoch) {
    __threadfence();
    __syncthreads();
    if (threadIdx.x == 0) {
        unsigned* cnt = &g_bcount[grp * 32];
        unsigned* ep  = &g_bepoch[grp * 32];
        if (atomicAdd(cnt, 1) == NGRP - 1) {
            atomicExch(cnt, 0);
            __threadfence();
            atomicAdd(ep, 1);
        } else {
            while (*(volatile unsigned*)ep == epoch) { }
        }
        epoch++;
    }
    __syncthreads();
}

// ---------------- embedding gather ----------------
__global__ void embed_k(const int* __restrict__ x, const float* __restrict__ emb) {
    int gid = blockIdx.x * blockDim.x + threadIdx.x;
    int r  = gid >> 5;
    int c4 = gid & 31;
    int t  = r >> 7;
    int b  = r & 127;
    int tok = x[b * TT + t];
    reinterpret_cast<float4*>(g_e)[(size_t)r * 32 + c4] =
        reinterpret_cast<const float4*>(emb)[(size_t)tok * 32 + c4];
}

// ---------------- 3xTF32 tensor-core GEMM + bias (unchanged from R7) ----------------
#define AS_LD 20
#define BS_LD 136
__global__ __launch_bounds__(256) void gemm_k(int a_sel, int c_sel,
        const float* __restrict__ W, const float* __restrict__ bias, int K)
{
    const float* A = a_sel ? g_seq : g_e;
    float*       C = c_sel ? g_XwB : g_XwF;

    __shared__ __align__(16) float As[2][128][AS_LD];
    __shared__ __align__(16) float Bs[2][16][BS_LD];

    const int m0   = blockIdx.x * 128;
    const int n0   = blockIdx.y * 128;
    const int tid  = threadIdx.x;
    const int lane = tid & 31;
    const int warp = tid >> 5;
    const int gid  = lane >> 2;
    const int tig  = lane & 3;
    const int wm   = warp & 3;
    const int wn   = warp >> 2;

    const unsigned sA = (unsigned)__cvta_generic_to_shared(&As[0][0][0]);
    const unsigned sB = (unsigned)__cvta_generic_to_shared(&Bs[0][0][0]);
    const unsigned bufA = 128 * AS_LD * 4;
    const unsigned bufB = 16 * BS_LD * 4;

    float acc[2][8][4];
#pragma unroll
    for (int mb = 0; mb < 2; ++mb)
#pragma unroll
        for (int nb = 0; nb < 8; ++nb)
#pragma unroll
            for (int r = 0; r < 4; ++r) acc[mb][nb][r] = 0.f;

    const int nk = K >> 4;

    auto load_tile = [&](int buf, int kt) {
#pragma unroll
        for (int i = 0; i < 2; ++i) {
            int id = tid + i * 256;
            int r = id >> 2, kq = id & 3;
            cpa16(sA + buf * bufA + (unsigned)((r * AS_LD + kq * 4) * 4),
                  A + (size_t)(m0 + r) * K + kt + kq * 4);
        }
#pragma unroll
        for (int i = 0; i < 2; ++i) {
            int id = tid + i * 256;
            int r = id >> 5, c4 = (id & 31) * 4;
            cpa16(sB + buf * bufB + (unsigned)((r * BS_LD + c4) * 4),
                  W + (size_t)(kt + r) * G4 + n0 + c4);
        }
        CPA_COMMIT();
    };

    load_tile(0, 0);
    CPA_WAIT0();
    __syncthreads();

    for (int kt = 0; kt < nk; ++kt) {
        const int cur = kt & 1;
        const bool more = (kt + 1) < nk;
        if (more) load_tile(cur ^ 1, (kt + 1) << 4);

#pragma unroll
        for (int kh = 0; kh < 2; ++kh) {
            const int k0 = kh * 8;
            unsigned ahi[2][4], alo[2][4];
#pragma unroll
            for (int mb = 0; mb < 2; ++mb) {
                const int rbase = wm * 32 + mb * 16 + gid;
#pragma unroll
                for (int r = 0; r < 4; ++r) {
                    float v = As[cur][rbase + (r & 1) * 8][k0 + tig + (r >> 1) * 4];
                    unsigned h = f2tf32(v);
                    ahi[mb][r] = h;
                    alo[mb][r] = f2tf32(v - __uint_as_float(h));
                }
            }
#pragma unroll
            for (int nb = 0; nb < 8; ++nb) {
                const int nc = wn * 64 + nb * 8 + gid;
                float b0 = Bs[cur][k0 + tig][nc];
                float b1 = Bs[cur][k0 + tig + 4][nc];
                unsigned bh[2], bl[2];
                bh[0] = f2tf32(b0); bl[0] = f2tf32(b0 - __uint_as_float(bh[0]));
                bh[1] = f2tf32(b1); bl[1] = f2tf32(b1 - __uint_as_float(bh[1]));
#pragma unroll
                for (int mb = 0; mb < 2; ++mb) mma_tf32(acc[mb][nb], ahi[mb], bh);
#pragma unroll
                for (int mb = 0; mb < 2; ++mb) mma_tf32(acc[mb][nb], ahi[mb], bl);
#pragma unroll
                for (int mb = 0; mb < 2; ++mb) mma_tf32(acc[mb][nb], alo[mb], bh);
            }
        }
        if (more) {
            CPA_WAIT0();
            __syncthreads();
        }
    }

#pragma unroll
    for (int mb = 0; mb < 2; ++mb) {
        const int row0 = m0 + wm * 32 + mb * 16 + gid;
#pragma unroll
        for (int nb = 0; nb < 8; ++nb) {
            const int col = n0 + wn * 64 + nb * 8 + tig * 2;
            float2 bv = *reinterpret_cast<const float2*>(bias + col);
            float2 v0 = make_float2(acc[mb][nb][0] + bv.x, acc[mb][nb][1] + bv.y);
            float2 v1 = make_float2(acc[mb][nb][2] + bv.x, acc[mb][nb][3] + bv.y);
            *reinterpret_cast<float2*>(C + (size_t)row0 * G4 + col)       = v0;
            *reinterpret_cast<float2*>(C + (size_t)(row0 + 8) * G4 + col) = v1;
        }
    }
}

// ---------------- persistent bidirectional LSTM: 512 threads, 4-way k-split ----------
// bid = dir*64 + bt*8 + nt. Same R7 exchange (global h double buffer, atomic 8-CTA
// group barrier). Thread org: tid = kq*128 + inner; inner = b_half*16 + n_grp (same
// 2-row x 2-col x 4-gate micro-kernel as R7 but over k in [kq*64, kq*64+64)).
// 16 warps -> 4 per SMSP: latency hiding. Partial sums reduced via smem.
// U smem layout gate-paired: float4 at [k][n_grp*2 + g2] = gates {2g2, 2g2+1} for
// cols (n, n+1)  -> 2 LDS.128 per k instead of 4 LDS.64.
__global__ __launch_bounds__(512) void lstm_persist_k(
        const float* __restrict__ Uf, const float* __restrict__ Ub, int write_seq)
{
    extern __shared__ float smp[];
    float*  Us  = smp;                                         // 32768 floats (128 KB)
    float (*sh)[260] = reinterpret_cast<float (*)[260]>(smp + 32768);   // h stage 16x260
    float2* red = reinterpret_cast<float2*>(smp + 32768 + 16 * 260);    // [8][4][128] f2

    const int bid = blockIdx.x;
    const int dir = bid >> 6;
    const int bt  = (bid >> 3) & 7;
    const int nt  = bid & 7;
    const int grp = bid >> 3;
    const int tid = threadIdx.x;
    const int kq    = tid >> 7;        // 0..3 k-quarter
    const int inner = tid & 127;

    const float* U  = dir ? Ub : Uf;
    const float* Xw = dir ? g_XwB : g_XwF;
    float* hbuf = g_state + (size_t)dir * 2 * BB * HH;

    // load U slice, gate-paired layout:
    // Us float4 idx = k*32 + ng*2 + g2  <- (U[k][2*g2*HH + col], U[k][(2*g2+1)*HH + col])
    // where col = nt*32 + ng*2
    for (int i = tid; i < 256 * 32; i += 512) {
        int k   = i >> 5;
        int f4  = i & 31;
        int ng  = f4 >> 1;
        int g2  = f4 & 1;
        int col = nt * 32 + ng * 2;
        const float* src = U + (size_t)k * G4 + (2 * g2) * HH + col;
        float2 a = *reinterpret_cast<const float2*>(src);
        float2 b = *reinterpret_cast<const float2*>(src + HH);
        reinterpret_cast<float4*>(Us)[i] = make_float4(a.x, a.y, b.x, b.y);
    }

    // zero my (bt, nt) patch of both h parity buffers
    for (int i = tid; i < 512; i += 512) {
        int r  = bt * 16 + (i >> 5);
        int cc = nt * 32 + (i & 31);
        __stcg(hbuf + (size_t)r * HH + cc, 0.f);
        __stcg(hbuf + (size_t)BB * HH + (size_t)r * HH + cc, 0.f);
    }

    unsigned epoch = 0;
    if (tid == 0) epoch = *(volatile unsigned*)&g_bepoch[grp * 32];
    grid_bar(grp, epoch);

    const int b_half = inner >> 4;
    const int n_grp  = inner & 15;
    const int nloc   = n_grp * 2;
    const int ngl    = nt * 32 + nloc;
    const int r0     = bt * 16 + b_half * 2;

    float2 cst[2] = {make_float2(0.f, 0.f), make_float2(0.f, 0.f)};

    for (int s = 0; s < TT; ++s) {
        const int t   = dir ? (TT - 1 - s) : s;
        const int par = s & 1;
        const float* hRead  = hbuf + (size_t)par * BB * HH;
        float*       hWrite = hbuf + (size_t)(par ^ 1) * BB * HH;

        // stage h tile (16 rows x 256) from L2: 1024 float4, 2 per thread
#pragma unroll
        for (int i = 0; i < 2; ++i) {
            int f = tid + i * 512;
            int r = f >> 6, cq = f & 63;
            *reinterpret_cast<float4*>(&sh[r][cq * 4]) =
                __ldcg(reinterpret_cast<const float4*>(
                    hRead + (size_t)(bt * 16 + r) * HH + cq * 4));
        }
        // Xw prefetch: gate threads only (kq == 0), consumed after reduction
        float2 x0[4], x1[4];
        if (kq == 0) {
            const float* xw0 = Xw + ((size_t)t * BB + r0) * G4 + ngl;
            const float* xw1 = xw0 + G4;
#pragma unroll
            for (int g = 0; g < 4; ++g) {
                x0[g] = *reinterpret_cast<const float2*>(xw0 + g * HH);
                x1[g] = *reinterpret_cast<const float2*>(xw1 + g * HH);
            }
        }
        __syncthreads();

        float2 acc[4][2];
#pragma unroll
        for (int g = 0; g < 4; ++g) {
            acc[g][0] = make_float2(0.f, 0.f);
            acc[g][1] = make_float2(0.f, 0.f);
        }

        const float* sr0 = sh[b_half * 2];
        const float* sr1 = sh[b_half * 2 + 1];
        const float4* Upair = reinterpret_cast<const float4*>(Us) + n_grp * 2;
        const int kbeg = kq * 64;

#pragma unroll 4
        for (int k4 = kbeg; k4 < kbeg + 64; k4 += 4) {
            float4 h0v = *reinterpret_cast<const float4*>(sr0 + k4);
            float4 h1v = *reinterpret_cast<const float4*>(sr1 + k4);
            const float h0a[4] = {h0v.x, h0v.y, h0v.z, h0v.w};
            const float h1a[4] = {h1v.x, h1v.y, h1v.z, h1v.w};
#pragma unroll
            for (int kk = 0; kk < 4; ++kk) {
                float4 u01 = Upair[(size_t)(k4 + kk) * 32];
                float4 u23 = Upair[(size_t)(k4 + kk) * 32 + 1];
                float2 hh0 = make_float2(h0a[kk], h0a[kk]);
                float2 hh1 = make_float2(h1a[kk], h1a[kk]);
                float2 u0 = make_float2(u01.x, u01.y);
                float2 u1 = make_float2(u01.z, u01.w);
                float2 u2 = make_float2(u23.x, u23.y);
                float2 u3 = make_float2(u23.z, u23.w);
                ffma2(acc[0][0], u0, hh0); ffma2(acc[0][1], u0, hh1);
                ffma2(acc[1][0], u1, hh0); ffma2(acc[1][1], u1, hh1);
                ffma2(acc[2][0], u2, hh0); ffma2(acc[2][1], u2, hh1);
                ffma2(acc[3][0], u3, hh0); ffma2(acc[3][1], u3, hh1);
            }
        }

        // cross-kq reduction: red[j][kq][inner], j = g*2+bb (conflict-free)
#pragma unroll
        for (int g = 0; g < 4; ++g)
#pragma unroll
            for (int bb = 0; bb < 2; ++bb)
                red[(size_t)(g * 2 + bb) * 512 + kq * 128 + inner] = acc[g][bb];
        __syncthreads();

        if (kq == 0) {
#pragma unroll
            for (int q = 1; q < 4; ++q)
#pragma unroll
                for (int j = 0; j < 8; ++j) {
                    float2 p = red[(size_t)j * 512 + q * 128 + inner];
                    acc[j >> 1][j & 1].x += p.x;
                    acc[j >> 1][j & 1].y += p.y;
                }

            // gates + state update for 2 batch rows
#pragma unroll
            for (int bb = 0; bb < 2; ++bb) {
                const float2* xg = bb ? x1 : x0;
                float zi0 = acc[0][bb].x + xg[0].x, zi1 = acc[0][bb].y + xg[0].y;
                float zf0 = acc[1][bb].x + xg[1].x, zf1 = acc[1][bb].y + xg[1].y;
                float zg0 = acc[2][bb].x + xg[2].x, zg1 = acc[2][bb].y + xg[2].y;
                float zo0 = acc[3][bb].x + xg[3].x, zo1 = acc[3][bb].y + xg[3].y;
                float c0 = sigf(zf0) * cst[bb].x + sigf(zi0) * tanhfast(zg0);
                float c1 = sigf(zf1) * cst[bb].y + sigf(zi1) * tanhfast(zg1);
                cst[bb] = make_float2(c0, c1);
                float h0 = sigf(zo0) * tanhfast(c0);
                float h1 = sigf(zo1) * tanhfast(c1);
                int r = r0 + bb;
                __stcg(reinterpret_cast<float2*>(hWrite + (size_t)r * HH + ngl),
                       make_float2(h0, h1));
                if (write_seq)
                    *reinterpret_cast<float2*>(
                        g_seq + ((size_t)t * BB + r) * (2 * HH) + dir * HH + ngl) =
                        make_float2(h0, h1);
            }
        }

        grid_bar(grp, epoch);
    }
}

// ---------------- final dense + softmax ----------------
__global__ void final_k(const float* __restrict__ Wd, const float* __restrict__ bd,
                        float* __restrict__ out)
{
    int b = blockIdx.x, lane = threadIdx.x;
    const float* hf = g_state;                    // dir0 final h (parity buf0)
    const float* hb = g_state + 2 * BB * HH;      // dir1 final h (parity buf0)
    float acc[CC];
#pragma unroll
    for (int c = 0; c < CC; ++c) acc[c] = 0.f;
    for (int k = lane; k < 2 * HH; k += 32) {
        float hv = (k < HH) ? hf[(size_t)b * HH + k] : hb[(size_t)b * HH + k - HH];
        const float* w = Wd + (size_t)k * CC;
#pragma unroll
        for (int c = 0; c < CC; ++c) acc[c] = fmaf(hv, w[c], acc[c]);
    }
#pragma unroll
    for (int c = 0; c < CC; ++c)
#pragma unroll
        for (int o = 16; o; o >>= 1) acc[c] += __shfl_down_sync(0xffffffffu, acc[c], o);
    if (lane == 0) {
        float m = -1e30f;
#pragma unroll
        for (int c = 0; c < CC; ++c) { acc[c] += bd[c]; m = fmaxf(m, acc[c]); }
        float e[CC], s = 0.f;
#pragma unroll
        for (int c = 0; c < CC; ++c) { e[c] = expf(acc[c] - m); s += e[c]; }
        float inv = 1.f / s;
#pragma unroll
        for (int c = 0; c < CC; ++c) out[b * CC + c] = e[c] * inv;
    }
}

extern "C" void kernel_launch(void* const* d_in, const int* in_sizes, int n_in,
                              void* d_out, int out_size)
{
    const int*   x   = (const int*)  d_in[0];
    const float* emb = (const float*)d_in[1];
    const float* W1f = (const float*)d_in[2];
    const float* U1f = (const float*)d_in[3];
    const float* b1f = (const float*)d_in[4];
    const float* W1b = (const float*)d_in[5];
    const float* U1b = (const float*)d_in[6];
    const float* b1b = (const float*)d_in[7];
    const float* W2f = (const float*)d_in[8];
    const float* U2f = (const float*)d_in[9];
    const float* b2f = (const float*)d_in[10];
    const float* W2b = (const float*)d_in[11];
    const float* U2b = (const float*)d_in[12];
    const float* b2b = (const float*)d_in[13];
    const float* Wd  = (const float*)d_in[14];
    const float* bd  = (const float*)d_in[15];
    float* out = (float*)d_out;

    // Us 128KB + sh 16*260*4 + red 8*512*8 = 131072 + 16640 + 32768 = 180480
    const int LSTM_SMEM = 131072 + 16 * 260 * 4 + 8 * 512 * 8;

    static int smem_set = 0;
    if (!smem_set) {
        cudaFuncSetAttribute(lstm_persist_k,
                             cudaFuncAttributeMaxDynamicSharedMemorySize, LSTM_SMEM);
        smem_set = 1;
    }

    embed_k<<<(MROWS * 32) / 256, 256>>>(x, emb);

    dim3 gg(MROWS / 128, G4 / 128);

    // layer 1
    gemm_k<<<gg, 256>>>(0, 0, W1f, b1f, DD);
    gemm_k<<<gg, 256>>>(0, 1, W1b, b1b, DD);
    lstm_persist_k<<<NCTA, 512, LSTM_SMEM>>>(U1f, U1b, 1);

    // layer 2
    gemm_k<<<gg, 256>>>(1, 0, W2f, b2f, 2 * HH);
    gemm_k<<<gg, 256>>>(1, 1, W2b, b2b, 2 * HH);
    lstm_persist_k<<<NCTA, 512, LSTM_SMEM>>>(U2f, U2b, 0);

    final_k<<<BB, 32>>>(Wd, bd, out);
}